// round 6
// baseline (speedup 1.0000x reference)
#include <cuda_runtime.h>

#define N_SAMPLES 32768
#define N_ITERS   16
#define KLEN      256
#define N_FRAMES  512
#define N_ATOMS   256
#define THREADS   1024
#define STEP      (N_SAMPLES / N_FRAMES)   // 64
#define N_VEC4    (N_SAMPLES / 4)          // 8192 float4s
#define W_VEC4    (KLEN / 4)               // 64 float4s per window

__device__ __forceinline__ void upd4(float4 v, int base, float& bv, int& bi)
{
    // process in increasing column order, strict > keeps FIRST max (jnp.argmax)
    if (v.x > bv) { bv = v.x; bi = base + 0; }
    if (v.y > bv) { bv = v.y; bi = base + 1; }
    if (v.z > bv) { bv = v.z; bi = base + 2; }
    if (v.w > bv) { bv = v.w; bi = base + 3; }
}

__device__ __forceinline__ int warp_argmax_vec(const float4* __restrict__ row4,
                                               int nvec4, int lane)
{
    float bv = -3.402823466e38f;
    int   bi = 0x7fffffff;
    // lane handles float4s lane, lane+32, ... (increasing base per lane)
    for (int c = lane; c < nvec4; c += 32)
        upd4(row4[c], c * 4, bv, bi);
    #pragma unroll
    for (int o = 16; o > 0; o >>= 1) {
        float ov = __shfl_down_sync(0xffffffffu, bv, o);
        int   oi = __shfl_down_sync(0xffffffffu, bi, o);
        if (ov > bv || (ov == bv && oi < bi)) { bv = ov; bi = oi; }
    }
    return bi;
}

__global__ __launch_bounds__(THREADS, 1)
void Model_67817533604348_kernel(const float* __restrict__ atom_sel,   // [16,256]
                                 const float* __restrict__ amps,       // [16,1]
                                 const float* __restrict__ sched,      // [16,512]
                                 const float* __restrict__ d,          // [256,256]
                                 float* __restrict__ out)              // [32768]
{
    __shared__ float s_atoms[N_ITERS][KLEN];   // 16 KB: amp-scaled selected rows
    __shared__ int   s_aidx[N_ITERS];
    __shared__ int   s_pos[N_ITERS];
    __shared__ float s_red[32];
    __shared__ float s_scale;

    const int tid  = threadIdx.x;
    const int wid  = tid >> 5;
    const int lane = tid & 31;

    // Task mapping (used in phases 2-4): thread owns 4 consecutive taps of one iter
    const int it = tid >> 6;            // iter (64 threads per iter)
    const int k0 = (tid & 63) << 2;     // first tap, multiple of 4

    // issue early (independent of everything)
    const float amp = amps[it];

    // ---------------- Phase 1: argmaxes ----------------
    // soft_dirac forward is an exact one-hot at argmax; softmax is monotone,
    // so argmax of raw logits suffices. First-occurrence tie-break preserved.
    if (wid < N_ITERS) {
        int bi = warp_argmax_vec((const float4*)(atom_sel + wid * N_ATOMS),
                                 N_ATOMS / 4, lane);
        if (lane == 0) s_aidx[wid] = bi;
    } else {
        const int i = wid - N_ITERS;
        int bi = warp_argmax_vec((const float4*)(sched + i * N_FRAMES),
                                 N_FRAMES / 4, lane);
        if (lane == 0) s_pos[i] = bi * STEP;   // impulse sample position (mult of 64)
    }
    __syncthreads();

    // ---------------- Phase 2a: dependent gather from d (latency chain: first) ---
    const float4 dv = *reinterpret_cast<const float4*>(d + s_aidx[it] * KLEN + k0);

    // ---------------- Phase 2b: early zero stores (fire-and-forget) --------------
    // Zeros don't depend on the scale (0 * scale = 0); write them now so the
    // STGs drain in the background during the rest of the kernel.
    int w4[N_ITERS];
    #pragma unroll
    for (int i = 0; i < N_ITERS; i++) w4[i] = s_pos[i] >> 2;   // window start, float4s

    float4* out4 = reinterpret_cast<float4*>(out);
    #pragma unroll
    for (int j = 0; j < N_VEC4 / THREADS; j++) {
        const int v = tid + j * THREADS;
        bool covered = false;
        #pragma unroll
        for (int i = 0; i < N_ITERS; i++)
            covered |= ((unsigned)(v - w4[i]) < (unsigned)W_VEC4);
        if (!covered) out4[v] = make_float4(0.f, 0.f, 0.f, 0.f);
    }

    // ---------------- Phase 2c: stage amp-scaled atom into smem ------------------
    *reinterpret_cast<float4*>(&s_atoms[it][k0]) =
        make_float4(amp * dv.x, amp * dv.y, amp * dv.z, amp * dv.w);
    __syncthreads();

    // ---------------- Phase 3: direct 16-way gather (no atomics) -----------------
    // Value at sample s = sum over windows j covering s. s0 - p_j is a multiple
    // of 4 (positions are multiples of 64), so aligned float4 LDS, conflict-free.
    // Overlapping windows compute bitwise-identical duplicates — benign.
    const int s0 = s_pos[it] + k0;
    float4 acc = make_float4(0.f, 0.f, 0.f, 0.f);
    #pragma unroll
    for (int j = 0; j < N_ITERS; j++) {
        const int off = s0 - (w4[j] << 2);
        if ((unsigned)off < (unsigned)KLEN) {
            const float4 a = *reinterpret_cast<const float4*>(&s_atoms[j][off]);
            acc.x += a.x; acc.y += a.y; acc.z += a.z; acc.w += a.w;
        }
    }
    const bool ok = s0 < N_SAMPLES;   // window truncated at 32768 (4-aligned cut)

    // ---------------- Phase 4: max-abs reduce over window samples ----------------
    float mx = ok ? fmaxf(fmaxf(fabsf(acc.x), fabsf(acc.y)),
                          fmaxf(fabsf(acc.z), fabsf(acc.w))) : 0.0f;
    #pragma unroll
    for (int o = 16; o > 0; o >>= 1)
        mx = fmaxf(mx, __shfl_xor_sync(0xffffffffu, mx, o));
    if (lane == 0) s_red[wid] = mx;
    __syncthreads();
    if (wid == 0) {
        float m = s_red[lane];
        #pragma unroll
        for (int o = 16; o > 0; o >>= 1)
            m = fmaxf(m, __shfl_xor_sync(0xffffffffu, m, o));
        if (lane == 0) s_scale = 1.0f / (m + 1e-8f);
    }
    __syncthreads();

    // ---------------- Phase 5: store window float4s only -------------------------
    const float scale = s_scale;
    if (ok) {
        acc.x *= scale; acc.y *= scale; acc.z *= scale; acc.w *= scale;
        *reinterpret_cast<float4*>(&out[s0]) = acc;
    }
}

extern "C" void kernel_launch(void* const* d_in, const int* in_sizes, int n_in,
                              void* d_out, int out_size) {
    // metadata order: x (unused), atom_selection, amps, sched_params, d
    const float* atom_sel = (const float*)d_in[1];
    const float* amps     = (const float*)d_in[2];
    const float* sched    = (const float*)d_in[3];
    const float* d        = (const float*)d_in[4];
    float* out            = (float*)d_out;

    Model_67817533604348_kernel<<<1, THREADS>>>(atom_sel, amps, sched, d, out);
}